// round 1
// baseline (speedup 1.0000x reference)
#include <cuda_runtime.h>
#include <math.h>

// Problem constants (TopKRouter: B=4, S=8192, D=1024, E=64, top_k=1)
#define DK      1024
#define NE      64
#define SEQ     8192
#define CAP     640
#define MAXTOK  32768

// GEMM tiling
#define BM 128
#define BN 64
#define BKT 16
#define TM 8
#define TN 4
// 256 threads: ty in [0,16) owns 8 rows, tx in [0,16) owns 4 cols

// Scratch (no allocations allowed -> __device__ globals)
__device__ int           g_argmax[MAXTOK];
__device__ float         g_topp[MAXTOK];
__device__ unsigned char g_keep[MAXTOK];

// ---------------------------------------------------------------------------
// Kernel 1: FP32 GEMM (logits = x @ W^T) fused with softmax top-1 epilogue.
// Writes full logits rows + per-token argmax + top probability.
// ---------------------------------------------------------------------------
__global__ __launch_bounds__(256, 2)
void gemm_router_kernel(const float* __restrict__ x,
                        const float* __restrict__ W,
                        float* __restrict__ logits,
                        int*   __restrict__ amax,
                        float* __restrict__ topp,
                        int M)
{
    __shared__ float As[BM][BKT];        // 8 KB
    __shared__ float Bs[BKT][BN + 4];    // 4.25 KB (pad to break store conflicts)

    const int tid = threadIdx.x;
    const int tx  = tid & 15;
    const int ty  = tid >> 4;
    const int m0  = blockIdx.x * BM;

    // A-tile loader mapping: 512 float4 per tile, thread handles f=tid and f=tid+256
    const int ar0 = tid >> 2;            // 0..63
    const int ac  = (tid & 3) * 4;       // float offset in k within tile
    // B-tile loader mapping: 256 float4 (16x64 floats transposed from W)
    const int bn  = tid >> 2;            // expert row 0..63
    const int bk  = (tid & 3) * 4;       // k offset within tile

    const float* a0p = x + (size_t)(m0 + ar0)      * DK + ac;
    const float* a1p = x + (size_t)(m0 + ar0 + 64) * DK + ac;
    const float* bp  = W + (size_t)bn * DK + bk;

    float4 pa0 = *(const float4*)(a0p);
    float4 pa1 = *(const float4*)(a1p);
    float4 pb  = *(const float4*)(bp);

    float acc[TM][TN];
    #pragma unroll
    for (int i = 0; i < TM; i++)
        #pragma unroll
        for (int j = 0; j < TN; j++) acc[i][j] = 0.0f;

    for (int k0 = 0; k0 < DK; k0 += BKT) {
        // commit prefetched tiles to shared
        *(float4*)&As[ar0][ac]      = pa0;
        *(float4*)&As[ar0 + 64][ac] = pa1;
        Bs[bk + 0][bn] = pb.x;
        Bs[bk + 1][bn] = pb.y;
        Bs[bk + 2][bn] = pb.z;
        Bs[bk + 3][bn] = pb.w;
        __syncthreads();

        // prefetch next K-slice while computing this one
        if (k0 + BKT < DK) {
            pa0 = *(const float4*)(a0p + k0 + BKT);
            pa1 = *(const float4*)(a1p + k0 + BKT);
            pb  = *(const float4*)(bp  + k0 + BKT);
        }

        #pragma unroll
        for (int kk = 0; kk < BKT; kk++) {
            float4 b4 = *(const float4*)&Bs[kk][tx * TN];
            float a[TM];
            #pragma unroll
            for (int i = 0; i < TM; i++) a[i] = As[ty * TM + i][kk];
            #pragma unroll
            for (int i = 0; i < TM; i++) {
                acc[i][0] = fmaf(a[i], b4.x, acc[i][0]);
                acc[i][1] = fmaf(a[i], b4.y, acc[i][1]);
                acc[i][2] = fmaf(a[i], b4.z, acc[i][2]);
                acc[i][3] = fmaf(a[i], b4.w, acc[i][3]);
            }
        }
        __syncthreads();
    }

    // Epilogue: each row's 64 logits live across the 16 lanes sharing ty
    // (half-warp: tids ty*16 .. ty*16+15). Reduce with shfl_xor (offsets < 16
    // stay within the half-warp).
    #pragma unroll
    for (int i = 0; i < TM; i++) {
        const int r = m0 + ty * TM + i;
        if (r >= M) continue;

        float4 v = make_float4(acc[i][0], acc[i][1], acc[i][2], acc[i][3]);
        *(float4*)&logits[(size_t)r * NE + tx * TN] = v;

        // local max + argmax (first-index tie-break to match jax top_k)
        float mx = acc[i][0];
        int   mi = tx * TN;
        #pragma unroll
        for (int j = 1; j < TN; j++) {
            if (acc[i][j] > mx) { mx = acc[i][j]; mi = tx * TN + j; }
        }
        #pragma unroll
        for (int off = 8; off >= 1; off >>= 1) {
            float om = __shfl_xor_sync(0xffffffffu, mx, off);
            int   oi = __shfl_xor_sync(0xffffffffu, mi, off);
            if (om > mx || (om == mx && oi < mi)) { mx = om; mi = oi; }
        }
        // softmax denominator
        float s = 0.0f;
        #pragma unroll
        for (int j = 0; j < TN; j++) s += __expf(acc[i][j] - mx) * 0.0f + expf(acc[i][j] - mx);
        #pragma unroll
        for (int off = 8; off >= 1; off >>= 1)
            s += __shfl_xor_sync(0xffffffffu, s, off);

        if (tx == 0) {
            amax[r] = mi;
            topp[r] = 1.0f / s;   // exp(mx-mx)/sum
        }
    }
}

// ---------------------------------------------------------------------------
// Kernel 2: per-(batch, expert) capacity scan. One block per (b,e).
// Computes inclusive rank of each assigned token; keep = rank <= CAP.
// Every token is written exactly once (by its argmax expert's block).
// ---------------------------------------------------------------------------
__global__ __launch_bounds__(256)
void scan_kernel(const int* __restrict__ amax, unsigned char* __restrict__ keep)
{
    const int b = blockIdx.x >> 6;        // / NE
    const int e = blockIdx.x & (NE - 1);
    const int* am = amax + (size_t)b * SEQ;
    unsigned char* kp = keep + (size_t)b * SEQ;

    const int lane = threadIdx.x & 31;
    const int wid  = threadIdx.x >> 5;
    __shared__ int warpsums[8];

    int running = 0;
    for (int base = 0; base < SEQ; base += 256) {
        const int s = base + threadIdx.x;
        const int m = (am[s] == e) ? 1 : 0;

        // warp inclusive scan
        int v = m;
        #pragma unroll
        for (int off = 1; off < 32; off <<= 1) {
            int t = __shfl_up_sync(0xffffffffu, v, off);
            if (lane >= off) v += t;
        }
        if (lane == 31) warpsums[wid] = v;
        __syncthreads();

        int excl = 0, tot = 0;
        #pragma unroll
        for (int w = 0; w < 8; w++) {
            int ws = warpsums[w];
            if (w < wid) excl += ws;
            tot += ws;
        }
        const int rank = running + excl + v;   // inclusive cumsum
        if (m) kp[s] = (rank <= CAP) ? 1 : 0;
        running += tot;
        __syncthreads();
    }
}

// ---------------------------------------------------------------------------
// Kernel 3: scatter one-hot expert_indices and router_probs (float 0/1, p).
// 16 threads per token, float4 stores -> fully coalesced.
// ---------------------------------------------------------------------------
__global__ __launch_bounds__(256)
void scatter_kernel(const int* __restrict__ amax,
                    const unsigned char* __restrict__ keep,
                    const float* __restrict__ topp,
                    float* __restrict__ ei,
                    float* __restrict__ rp,
                    int M)
{
    const int token  = blockIdx.x * 16 + (threadIdx.x >> 4);
    const int lane16 = threadIdx.x & 15;
    if (token >= M) return;

    const int   am = amax[token];
    const float tp = topp[token];
    const int   kp = keep[token];

    float4 e = make_float4(0.f, 0.f, 0.f, 0.f);
    float4 r = make_float4(0.f, 0.f, 0.f, 0.f);
    const int c0 = lane16 * 4;
    if (kp && am >= c0 && am < c0 + 4) {
        ((float*)&e)[am - c0] = 1.0f;
        ((float*)&r)[am - c0] = tp;
    }
    *(float4*)&ei[(size_t)token * NE + c0] = e;
    *(float4*)&rp[(size_t)token * NE + c0] = r;
}

// ---------------------------------------------------------------------------
extern "C" void kernel_launch(void* const* d_in, const int* in_sizes, int n_in,
                              void* d_out, int out_size)
{
    const float* x = (const float*)d_in[0];
    const float* W = (const float*)d_in[1];
    (void)n_in; (void)out_size;

    const int M = in_sizes[0] / DK;          // B*S tokens (32768)
    const int B = M / SEQ;

    float* out = (float*)d_out;
    const size_t BSE = (size_t)M * NE;
    float* ei = out;                 // expert_indices (as float 0/1)
    float* rp = out + BSE;           // router_probs
    float* lg = out + 2 * BSE;       // logits

    int* amax;            cudaGetSymbolAddress((void**)&amax, g_argmax);
    float* topp;          cudaGetSymbolAddress((void**)&topp, g_topp);
    unsigned char* keep;  cudaGetSymbolAddress((void**)&keep, g_keep);

    gemm_router_kernel<<<(M + BM - 1) / BM, 256>>>(x, W, lg, amax, topp, M);
    scan_kernel<<<B * NE, 256>>>(amax, keep);
    scatter_kernel<<<(M + 15) / 16, 256>>>(amax, keep, topp, ei, rp, M);
}

// round 2
// speedup vs baseline: 1.1044x; 1.1044x over previous
#include <cuda_runtime.h>
#include <math.h>

// Problem constants (TopKRouter: B=4, S=8192, D=1024, E=64, top_k=1)
#define DK      1024
#define NE      64
#define SEQ     8192
#define CAP     640
#define MAXTOK  32768

// GEMM tiling
#define BM 128
#define BN 64
#define BKT 16
#define TM 8
#define TN 4
#define APAD 2   // As row stride BM+2: transposing STS conflict-free, 8B-aligned rows
// 256 threads: ty in [0,16) owns 8 rows, tx in [0,16) owns 4 cols

// Scratch (no allocations allowed -> __device__ globals)
__device__ int           g_argmax[MAXTOK];
__device__ float         g_topp[MAXTOK];
__device__ unsigned char g_keep[MAXTOK];

typedef unsigned long long u64;

// Packed fp32x2 FMA (Blackwell): d.lo += a.lo*b.lo ; d.hi += a.hi*b.hi
__device__ __forceinline__ void ffma2(u64& d, u64 a, u64 b) {
    asm("fma.rn.f32x2 %0, %1, %2, %0;" : "+l"(d) : "l"(a), "l"(b));
}
__device__ __forceinline__ u64 pack2(float x) {
    u64 r; asm("mov.b64 %0, {%1, %1};" : "=l"(r) : "f"(x)); return r;
}
__device__ __forceinline__ void unpack2(u64 v, float& lo, float& hi) {
    asm("mov.b64 {%0, %1}, %2;" : "=f"(lo), "=f"(hi) : "l"(v));
}

// ---------------------------------------------------------------------------
// Kernel 1: FP32 GEMM (logits = x @ W^T) via packed f32x2 FMA, fused with
// softmax top-1 epilogue. Writes logits + per-token argmax + top probability.
// ---------------------------------------------------------------------------
__global__ __launch_bounds__(256, 2)
void gemm_router_kernel(const float* __restrict__ x,
                        const float* __restrict__ W,
                        float* __restrict__ logits,
                        int*   __restrict__ amax,
                        float* __restrict__ topp,
                        int M)
{
    __shared__ float As[BKT][BM + APAD];   // transposed A tile: As[k][m]
    __shared__ float Bs[BKT][BN + 4];      // Bs[k][e]

    const int tid = threadIdx.x;
    const int tx  = tid & 15;
    const int ty  = tid >> 4;
    const int m0  = blockIdx.x * BM;

    // A-tile loader: each thread fetches float4 of rows ar0 and ar0+64
    const int ar0 = tid >> 2;            // 0..63
    const int ac  = (tid & 3) * 4;       // k offset within tile
    // B-tile loader
    const int bn  = tid >> 2;            // expert row 0..63
    const int bk  = (tid & 3) * 4;       // k offset within tile

    const float* a0p = x + (size_t)(m0 + ar0)      * DK + ac;
    const float* a1p = x + (size_t)(m0 + ar0 + 64) * DK + ac;
    const float* bp  = W + (size_t)bn * DK + bk;

    float4 pa0 = *(const float4*)(a0p);
    float4 pa1 = *(const float4*)(a1p);
    float4 pb  = *(const float4*)(bp);

    // Packed accumulators: acc2[i2][j] holds rows (ty*8+2*i2, +1), col tx*4+j
    u64 acc2[TM / 2][TN];
    #pragma unroll
    for (int i = 0; i < TM / 2; i++)
        #pragma unroll
        for (int j = 0; j < TN; j++) acc2[i][j] = 0ULL;

    for (int k0 = 0; k0 < DK; k0 += BKT) {
        // commit prefetched tiles to shared (A transposed)
        As[ac + 0][ar0] = pa0.x;  As[ac + 1][ar0] = pa0.y;
        As[ac + 2][ar0] = pa0.z;  As[ac + 3][ar0] = pa0.w;
        As[ac + 0][ar0 + 64] = pa1.x;  As[ac + 1][ar0 + 64] = pa1.y;
        As[ac + 2][ar0 + 64] = pa1.z;  As[ac + 3][ar0 + 64] = pa1.w;
        Bs[bk + 0][bn] = pb.x;
        Bs[bk + 1][bn] = pb.y;
        Bs[bk + 2][bn] = pb.z;
        Bs[bk + 3][bn] = pb.w;
        __syncthreads();

        // prefetch next K-slice while computing this one
        if (k0 + BKT < DK) {
            pa0 = *(const float4*)(a0p + k0 + BKT);
            pa1 = *(const float4*)(a1p + k0 + BKT);
            pb  = *(const float4*)(bp  + k0 + BKT);
        }

        #pragma unroll
        for (int kk = 0; kk < BKT; kk++) {
            // A row-pairs: 64-bit broadcast loads (8B-aligned: row stride 520B)
            u64 a2[TM / 2];
            #pragma unroll
            for (int q = 0; q < TM / 2; q++)
                a2[q] = *(const u64*)&As[kk][ty * TM + 2 * q];

            float4 b4 = *(const float4*)&Bs[kk][tx * TN];
            u64 b2[TN];
            b2[0] = pack2(b4.x); b2[1] = pack2(b4.y);
            b2[2] = pack2(b4.z); b2[3] = pack2(b4.w);

            #pragma unroll
            for (int i = 0; i < TM / 2; i++) {
                ffma2(acc2[i][0], a2[i], b2[0]);
                ffma2(acc2[i][1], a2[i], b2[1]);
                ffma2(acc2[i][2], a2[i], b2[2]);
                ffma2(acc2[i][3], a2[i], b2[3]);
            }
        }
        __syncthreads();
    }

    // Unpack to scalar accumulators acc[i][j] (row ty*8+i, col tx*4+j)
    float acc[TM][TN];
    #pragma unroll
    for (int i2 = 0; i2 < TM / 2; i2++)
        #pragma unroll
        for (int j = 0; j < TN; j++)
            unpack2(acc2[i2][j], acc[2 * i2][j], acc[2 * i2 + 1][j]);

    // Epilogue: each row's 64 logits live across the 16 lanes sharing ty
    // (half-warp). Reduce with shfl_xor (offsets < 16 stay within half-warp).
    #pragma unroll
    for (int i = 0; i < TM; i++) {
        const int r = m0 + ty * TM + i;
        if (r >= M) continue;

        float4 v = make_float4(acc[i][0], acc[i][1], acc[i][2], acc[i][3]);
        *(float4*)&logits[(size_t)r * NE + tx * TN] = v;

        // local max + argmax (first-index tie-break to match jax top_k)
        float mx = acc[i][0];
        int   mi = tx * TN;
        #pragma unroll
        for (int j = 1; j < TN; j++) {
            if (acc[i][j] > mx) { mx = acc[i][j]; mi = tx * TN + j; }
        }
        #pragma unroll
        for (int off = 8; off >= 1; off >>= 1) {
            float om = __shfl_xor_sync(0xffffffffu, mx, off);
            int   oi = __shfl_xor_sync(0xffffffffu, mi, off);
            if (om > mx || (om == mx && oi < mi)) { mx = om; mi = oi; }
        }
        // softmax denominator
        float s = 0.0f;
        #pragma unroll
        for (int j = 0; j < TN; j++) s += expf(acc[i][j] - mx);
        #pragma unroll
        for (int off = 8; off >= 1; off >>= 1)
            s += __shfl_xor_sync(0xffffffffu, s, off);

        if (tx == 0) {
            amax[r] = mi;
            topp[r] = 1.0f / s;   // exp(mx-mx)/sum
        }
    }
}

// ---------------------------------------------------------------------------
// Kernel 2: per-(batch, expert) capacity scan. One block per (b,e).
// ---------------------------------------------------------------------------
__global__ __launch_bounds__(256)
void scan_kernel(const int* __restrict__ amax, unsigned char* __restrict__ keep)
{
    const int b = blockIdx.x >> 6;        // / NE
    const int e = blockIdx.x & (NE - 1);
    const int* am = amax + (size_t)b * SEQ;
    unsigned char* kp = keep + (size_t)b * SEQ;

    const int lane = threadIdx.x & 31;
    const int wid  = threadIdx.x >> 5;
    __shared__ int warpsums[8];

    int running = 0;
    for (int base = 0; base < SEQ; base += 256) {
        const int s = base + threadIdx.x;
        const int m = (am[s] == e) ? 1 : 0;

        // warp inclusive scan
        int v = m;
        #pragma unroll
        for (int off = 1; off < 32; off <<= 1) {
            int t = __shfl_up_sync(0xffffffffu, v, off);
            if (lane >= off) v += t;
        }
        if (lane == 31) warpsums[wid] = v;
        __syncthreads();

        int excl = 0, tot = 0;
        #pragma unroll
        for (int w = 0; w < 8; w++) {
            int ws = warpsums[w];
            if (w < wid) excl += ws;
            tot += ws;
        }
        const int rank = running + excl + v;   // inclusive cumsum
        if (m) kp[s] = (rank <= CAP) ? 1 : 0;
        running += tot;
        __syncthreads();
    }
}

// ---------------------------------------------------------------------------
// Kernel 3: scatter one-hot expert_indices and router_probs.
// ---------------------------------------------------------------------------
__global__ __launch_bounds__(256)
void scatter_kernel(const int* __restrict__ amax,
                    const unsigned char* __restrict__ keep,
                    const float* __restrict__ topp,
                    float* __restrict__ ei,
                    float* __restrict__ rp,
                    int M)
{
    const int token  = blockIdx.x * 16 + (threadIdx.x >> 4);
    const int lane16 = threadIdx.x & 15;
    if (token >= M) return;

    const int   am = amax[token];
    const float tp = topp[token];
    const int   kp = keep[token];

    float4 e = make_float4(0.f, 0.f, 0.f, 0.f);
    float4 r = make_float4(0.f, 0.f, 0.f, 0.f);
    const int c0 = lane16 * 4;
    if (kp && am >= c0 && am < c0 + 4) {
        ((float*)&e)[am - c0] = 1.0f;
        ((float*)&r)[am - c0] = tp;
    }
    *(float4*)&ei[(size_t)token * NE + c0] = e;
    *(float4*)&rp[(size_t)token * NE + c0] = r;
}

// ---------------------------------------------------------------------------
extern "C" void kernel_launch(void* const* d_in, const int* in_sizes, int n_in,
                              void* d_out, int out_size)
{
    const float* x = (const float*)d_in[0];
    const float* W = (const float*)d_in[1];
    (void)n_in; (void)out_size;

    const int M = in_sizes[0] / DK;          // B*S tokens (32768)
    const int B = M / SEQ;

    float* out = (float*)d_out;
    const size_t BSE = (size_t)M * NE;
    float* ei = out;                 // expert_indices (as float 0/1)
    float* rp = out + BSE;           // router_probs
    float* lg = out + 2 * BSE;       // logits

    int* amax;            cudaGetSymbolAddress((void**)&amax, g_argmax);
    float* topp;          cudaGetSymbolAddress((void**)&topp, g_topp);
    unsigned char* keep;  cudaGetSymbolAddress((void**)&keep, g_keep);

    gemm_router_kernel<<<(M + BM - 1) / BM, 256>>>(x, W, lg, amax, topp, M);
    scan_kernel<<<B * NE, 256>>>(amax, keep);
    scatter_kernel<<<(M + 15) / 16, 256>>>(amax, keep, topp, ei, rp, M);
}